// round 1
// baseline (speedup 1.0000x reference)
#include <cuda_runtime.h>
#include <math.h>

// Problem constants (B=4, N=4096, D=1024, E=8, K=2)
#define TT 16384              // tokens = B*N
#define DD 1024               // model dim
#define HH 2048               // hidden = 2*D
#define EE 8                  // experts
#define SLOTS (2 * TT)        // token-expert assignment slots (K=2)

// ---------------- scratch (no allocations allowed -> __device__ globals) ---
__device__ int   g_cnt[EE];                       // per-expert routed count
__device__ int   g_tok [EE][TT];                  // gathered token index
__device__ int   g_slot[EE][TT];                  // slot = 2*t + k
__device__ float g_gate[SLOTS];                   // softmax gate per slot
__device__ float g_h[(size_t)SLOTS * HH];         // hidden activations (256MB)
__device__ float g_y[(size_t)SLOTS * DD];         // per-slot expert output (128MB)

// fp32 -> tf32 (round-to-nearest) returning raw bits
__device__ __forceinline__ unsigned tf32_bits(float x) {
    unsigned r;
    asm("cvt.rna.tf32.f32 %0, %1;" : "=r"(r) : "f"(x));
    return r;
}
__device__ __forceinline__ float tf32f(float x) {
    return __uint_as_float(tf32_bits(x));
}

// ---------------------------------------------------------------- init ----
__global__ void moe_init() {
    if (threadIdx.x < EE) g_cnt[threadIdx.x] = 0;
}

// -------------------------------------------------------------- gating ----
// One warp per token. Lanes stride over D (coalesced x reads); Wg staged
// transposed in smem so per-lane reads are conflict-free.
__global__ void __launch_bounds__(256) moe_gate(
    const float* __restrict__ x, const float* __restrict__ Wg,
    const float* __restrict__ bg)
{
    __shared__ float sWgT[EE][DD];   // 32 KB
    const int tid = threadIdx.x;
    for (int i = tid; i < EE * DD; i += 256) {
        int e = i >> 10, d = i & (DD - 1);
        sWgT[e][d] = Wg[d * EE + e];
    }
    __syncthreads();

    const int warp = tid >> 5, lane = tid & 31;
    const int t = blockIdx.x * 8 + warp;   // grid = TT/8 blocks

    float acc[EE];
#pragma unroll
    for (int e = 0; e < EE; e++) acc[e] = 0.f;

    const float* xr = x + (size_t)t * DD;
    for (int d = lane; d < DD; d += 32) {
        float xv = xr[d];
#pragma unroll
        for (int e = 0; e < EE; e++) acc[e] += xv * sWgT[e][d];
    }
#pragma unroll
    for (int e = 0; e < EE; e++) {
#pragma unroll
        for (int off = 16; off > 0; off >>= 1)
            acc[e] += __shfl_xor_sync(0xffffffffu, acc[e], off);
    }

    if (lane == 0) {
        float l[EE];
#pragma unroll
        for (int e = 0; e < EE; e++) l[e] = acc[e] + bg[e];
        // top-2, first-index wins on ties (matches jax.lax.top_k)
        int i0 = 0; float m0 = l[0];
#pragma unroll
        for (int e = 1; e < EE; e++) if (l[e] > m0) { m0 = l[e]; i0 = e; }
        int i1 = -1; float m1 = -1e30f;
#pragma unroll
        for (int e = 0; e < EE; e++)
            if (e != i0 && l[e] > m1) { m1 = l[e]; i1 = e; }
        float e1 = expf(m1 - m0);
        float inv = 1.0f / (1.0f + e1);
        float gv0 = inv, gv1 = e1 * inv;

        int p0 = atomicAdd(&g_cnt[i0], 1);
        g_tok[i0][p0] = t;  g_slot[i0][p0] = 2 * t;
        int p1 = atomicAdd(&g_cnt[i1], 1);
        g_tok[i1][p1] = t;  g_slot[i1][p1] = 2 * t + 1;
        g_gate[2 * t]     = gv0;
        g_gate[2 * t + 1] = gv1;
    }
}

// -------------------------------------------------- grouped gather-GEMM ----
// P1: h[slot] = relu( x[tok] @ W1[e] + b1[e] )   (K=1024, N=2048)
// P2: y[slot] =       h[slot] @ W2[e] + b2[e]    (K=2048, N=1024)
// Tile: BM=128, BN=64, BK=16, 256 threads, 8 warps of 32x32 (m16n8k8 tf32).
template <bool P1>
__global__ void __launch_bounds__(256) moe_gemm(
    const float* __restrict__ xin,      // x (P1) — ignored in P2
    const float* __restrict__ Wall,     // W1 or W2 : [E, KD, NC]
    const float* __restrict__ ball)     // b1 or b2 : [E, NC]
{
    constexpr int KD = P1 ? DD : HH;
    constexpr int NC = P1 ? HH : DD;

    const int e = blockIdx.z;
    const int cnt = g_cnt[e];
    const int mbase = blockIdx.y * 128;
    if (mbase >= cnt) return;
    const int nbase = blockIdx.x * 64;

    const float* W    = Wall + (size_t)e * KD * NC;
    const float* bias = ball + (size_t)e * NC;
    const float* Abase = P1 ? xin : g_h;

    __shared__ float As[16][136];   // (136 % 32 == 8) -> conflict-free frags
    __shared__ float Bs[16][72];    // (72  % 32 == 8)
    __shared__ int sSrc[128], sDst[128];

    const int tid = threadIdx.x;
    for (int i = tid; i < 128; i += 256) {
        int m = mbase + i;
        int mc = m < cnt ? m : cnt - 1;     // clamp: loads valid, stores masked
        sSrc[i] = P1 ? g_tok[e][mc] : g_slot[e][mc];
        sDst[i] = g_slot[e][mc];
    }
    __syncthreads();

    // A loads: c4 = tid>>6 (0..3 -> 4 cols), r = tid&63 (+64) : conflict-free STS
    const int ac = (tid >> 6) * 4;
    const int ar = tid & 63;
    const float* ap0 = Abase + (size_t)sSrc[ar]      * KD + ac;
    const float* ap1 = Abase + (size_t)sSrc[ar + 64] * KD + ac;
    // B loads: 16 rows x 64 cols, one float4/thread
    const int br = tid >> 4;            // 0..15
    const int bc = (tid & 15) * 4;      // 0..60
    const float* bp = W + (size_t)br * NC + nbase + bc;

    const int warp = tid >> 5, lane = tid & 31;
    const int wm = (warp & 3) * 32;     // warp row base
    const int wn = (warp >> 2) * 32;    // warp col base
    const int grp = lane >> 2, q = lane & 3;

    float acc[2][4][4];
#pragma unroll
    for (int a = 0; a < 2; a++)
#pragma unroll
        for (int b = 0; b < 4; b++)
#pragma unroll
            for (int c = 0; c < 4; c++) acc[a][b][c] = 0.f;

    for (int k0 = 0; k0 < KD; k0 += 16) {
        float4 va0 = *(const float4*)(ap0 + k0);
        float4 va1 = *(const float4*)(ap1 + k0);
        float4 vb  = *(const float4*)(bp + (size_t)k0 * NC);
        __syncthreads();    // previous tile fully consumed
        As[ac + 0][ar]      = tf32f(va0.x);
        As[ac + 1][ar]      = tf32f(va0.y);
        As[ac + 2][ar]      = tf32f(va0.z);
        As[ac + 3][ar]      = tf32f(va0.w);
        As[ac + 0][ar + 64] = tf32f(va1.x);
        As[ac + 1][ar + 64] = tf32f(va1.y);
        As[ac + 2][ar + 64] = tf32f(va1.z);
        As[ac + 3][ar + 64] = tf32f(va1.w);
        Bs[br][bc + 0] = tf32f(vb.x);
        Bs[br][bc + 1] = tf32f(vb.y);
        Bs[br][bc + 2] = tf32f(vb.z);
        Bs[br][bc + 3] = tf32f(vb.w);
        __syncthreads();

#pragma unroll
        for (int kk = 0; kk < 16; kk += 8) {
            unsigned a[2][4], b[4][2];
#pragma unroll
            for (int mi = 0; mi < 2; mi++) {
                int r0 = wm + mi * 16 + grp;
                a[mi][0] = __float_as_uint(As[kk + q    ][r0]);
                a[mi][1] = __float_as_uint(As[kk + q    ][r0 + 8]);
                a[mi][2] = __float_as_uint(As[kk + q + 4][r0]);
                a[mi][3] = __float_as_uint(As[kk + q + 4][r0 + 8]);
            }
#pragma unroll
            for (int ni = 0; ni < 4; ni++) {
                int c0 = wn + ni * 8 + grp;
                b[ni][0] = __float_as_uint(Bs[kk + q    ][c0]);
                b[ni][1] = __float_as_uint(Bs[kk + q + 4][c0]);
            }
#pragma unroll
            for (int mi = 0; mi < 2; mi++)
#pragma unroll
                for (int ni = 0; ni < 4; ni++) {
                    asm volatile(
                        "mma.sync.aligned.m16n8k8.row.col.f32.tf32.tf32.f32 "
                        "{%0,%1,%2,%3}, {%4,%5,%6,%7}, {%8,%9}, {%0,%1,%2,%3};"
                        : "+f"(acc[mi][ni][0]), "+f"(acc[mi][ni][1]),
                          "+f"(acc[mi][ni][2]), "+f"(acc[mi][ni][3])
                        : "r"(a[mi][0]), "r"(a[mi][1]), "r"(a[mi][2]), "r"(a[mi][3]),
                          "r"(b[ni][0]), "r"(b[ni][1]));
                }
        }
    }

    // epilogue: bias (+relu), scatter by slot
    float* Out = P1 ? g_h : g_y;
#pragma unroll
    for (int mi = 0; mi < 2; mi++) {
#pragma unroll
        for (int ni = 0; ni < 4; ni++) {
            int col = nbase + wn + ni * 8 + q * 2;
            float bv0 = bias[col], bv1 = bias[col + 1];
#pragma unroll
            for (int h = 0; h < 2; h++) {
                int rl = wm + mi * 16 + grp + h * 8;
                if (mbase + rl < cnt) {
                    float v0 = acc[mi][ni][2 * h]     + bv0;
                    float v1 = acc[mi][ni][2 * h + 1] + bv1;
                    if (P1) { v0 = fmaxf(v0, 0.f); v1 = fmaxf(v1, 0.f); }
                    float* op = Out + (size_t)sDst[rl] * NC + col;
                    *(float2*)op = make_float2(v0, v1);
                }
            }
        }
    }
}

// ------------------------------------------------------------- combine ----
// out[t] = g0 * y[2t] + g1 * y[2t+1]
__global__ void __launch_bounds__(256) moe_combine(float* __restrict__ out) {
    int i = blockIdx.x * 256 + threadIdx.x;   // over TT*DD/4 float4s
    int t  = i >> 8;                           // DD/4 = 256
    int d4 = i & 255;
    float gv0 = g_gate[2 * t], gv1 = g_gate[2 * t + 1];
    const float4* y4 = (const float4*)g_y;
    float4 a = y4[(size_t)(2 * t) * 256 + d4];
    float4 b = y4[(size_t)(2 * t) * 256 + 256 + d4];
    float4 r;
    r.x = gv0 * a.x + gv1 * b.x;
    r.y = gv0 * a.y + gv1 * b.y;
    r.z = gv0 * a.z + gv1 * b.z;
    r.w = gv0 * a.w + gv1 * b.w;
    ((float4*)out)[i] = r;
}

// ---------------------------------------------------------------- launch --
extern "C" void kernel_launch(void* const* d_in, const int* in_sizes, int n_in,
                              void* d_out, int out_size) {
    // metadata order: x, Wg, bg, W1, b1, W2, b2
    const float* x  = (const float*)d_in[0];
    const float* Wg = (const float*)d_in[1];
    const float* bg = (const float*)d_in[2];
    const float* W1 = (const float*)d_in[3];
    const float* b1 = (const float*)d_in[4];
    const float* W2 = (const float*)d_in[5];
    const float* b2 = (const float*)d_in[6];
    float* out = (float*)d_out;

    moe_init<<<1, 32>>>();
    moe_gate<<<TT / 8, 256>>>(x, Wg, bg);
    {   // GEMM1: N=HH tiles of 64, worst-case M tiles, E experts
        dim3 g(HH / 64, TT / 128, EE);
        moe_gemm<true><<<g, 256>>>(x, W1, b1);
    }
    {   // GEMM2: N=DD tiles of 64
        dim3 g(DD / 64, TT / 128, EE);
        moe_gemm<false><<<g, 256>>>(x, W2, b2);
    }
    moe_combine<<<(TT * DD / 4) / 256, 256>>>(out);
}

// round 13
// speedup vs baseline: 1.4971x; 1.4971x over previous
#include <cuda_runtime.h>
#include <math.h>
#include <cstdint>

// Problem constants (B=4, N=4096, D=1024, E=8, K=2)
#define TT 16384              // tokens = B*N
#define DD 1024               // model dim
#define HH 2048               // hidden = 2*D
#define EE 8                  // experts
#define SLOTS (2 * TT)        // token-expert assignment slots (K=2)

// ---------------- scratch (no allocations allowed -> __device__ globals) ---
__device__ int   g_cnt[EE];
__device__ int   g_tok [EE][TT];
__device__ int   g_slot[EE][TT];
__device__ float g_gate[SLOTS];
__device__ float g_xt[(size_t)TT * DD];            // tf32-rounded x (64 MB)
__device__ float g_h[(size_t)SLOTS * HH];          // tf32-rounded hidden (256 MB)
__device__ float g_y[(size_t)SLOTS * DD];          // fp32 expert outputs (128 MB)
__device__ float g_W1t[(size_t)EE * HH * DD];      // W1^T [E][N=HH][K=DD], tf32
__device__ float g_W2t[(size_t)EE * DD * HH];      // W2^T [E][N=DD][K=HH], tf32

// ------------------------------------------------------------- helpers ----
__device__ __forceinline__ float tf32f(float x) {
    unsigned r;
    asm("cvt.rna.tf32.f32 %0, %1;" : "=r"(r) : "f"(x));
    return __uint_as_float(r);
}
__device__ __forceinline__ uint32_t smem_u32(const void* p) {
    uint32_t a;
    asm("{ .reg .u64 t; cvta.to.shared.u64 t, %1; cvt.u32.u64 %0, t; }"
        : "=r"(a) : "l"(p));
    return a;
}
__device__ __forceinline__ void cpa16(uint32_t saddr, const float* g) {
    asm volatile("cp.async.cg.shared.global [%0], [%1], 16;"
                 :: "r"(saddr), "l"(g) : "memory");
}
#define CP_COMMIT() asm volatile("cp.async.commit_group;" ::: "memory")
#define CP_WAIT1()  asm volatile("cp.async.wait_group 1;" ::: "memory")
#define CP_WAIT0()  asm volatile("cp.async.wait_group 0;" ::: "memory")

// ---------------------------------------------------------------- init ----
__global__ void moe_init() {
    if (threadIdx.x < EE) g_cnt[threadIdx.x] = 0;
}

// ----------------------------------------------------- x -> tf32 round ----
__global__ void __launch_bounds__(256) x_cvt(const float4* __restrict__ x) {
    int i = blockIdx.x * 256 + threadIdx.x;   // TT*DD/4 elements
    float4 v = x[i];
    v.x = tf32f(v.x); v.y = tf32f(v.y); v.z = tf32f(v.z); v.w = tf32f(v.w);
    ((float4*)g_xt)[i] = v;
}

// -------------------------------------------------------------- gating ----
__global__ void __launch_bounds__(256) moe_gate(
    const float* __restrict__ x, const float* __restrict__ Wg,
    const float* __restrict__ bg)
{
    __shared__ float sWgT[EE][DD];
    const int tid = threadIdx.x;
    for (int i = tid; i < EE * DD; i += 256) {
        int e = i >> 10, d = i & (DD - 1);
        sWgT[e][d] = Wg[d * EE + e];
    }
    __syncthreads();

    const int warp = tid >> 5, lane = tid & 31;
    const int t = blockIdx.x * 8 + warp;

    float acc[EE];
#pragma unroll
    for (int e = 0; e < EE; e++) acc[e] = 0.f;

    const float* xr = x + (size_t)t * DD;
    for (int d = lane; d < DD; d += 32) {
        float xv = xr[d];
#pragma unroll
        for (int e = 0; e < EE; e++) acc[e] += xv * sWgT[e][d];
    }
#pragma unroll
    for (int e = 0; e < EE; e++) {
#pragma unroll
        for (int off = 16; off > 0; off >>= 1)
            acc[e] += __shfl_xor_sync(0xffffffffu, acc[e], off);
    }

    if (lane == 0) {
        float l[EE];
#pragma unroll
        for (int e = 0; e < EE; e++) l[e] = acc[e] + bg[e];
        int i0 = 0; float m0 = l[0];
#pragma unroll
        for (int e = 1; e < EE; e++) if (l[e] > m0) { m0 = l[e]; i0 = e; }
        int i1 = -1; float m1 = -1e30f;
#pragma unroll
        for (int e = 0; e < EE; e++)
            if (e != i0 && l[e] > m1) { m1 = l[e]; i1 = e; }
        float e1 = expf(m1 - m0);
        float inv = 1.0f / (1.0f + e1);

        int p0 = atomicAdd(&g_cnt[i0], 1);
        g_tok[i0][p0] = t;  g_slot[i0][p0] = 2 * t;
        int p1 = atomicAdd(&g_cnt[i1], 1);
        g_tok[i1][p1] = t;  g_slot[i1][p1] = 2 * t + 1;
        g_gate[2 * t]     = inv;
        g_gate[2 * t + 1] = e1 * inv;
    }
}

// --------------------------------------- weight transpose + tf32 convert --
// W [E][K][N] (N contiguous) -> Wt [E][N][K] (K contiguous), tf32-rounded.
template <bool ONE>
__global__ void __launch_bounds__(256) transpose_cvt(const float* __restrict__ src) {
    constexpr int K = ONE ? DD : HH;
    constexpr int N = ONE ? HH : DD;
    float* dst = ONE ? g_W1t : g_W2t;
    __shared__ float t[32][33];
    const size_t esz = (size_t)K * N;
    const float* s = src + blockIdx.z * esz;
    float* d = dst + blockIdx.z * esz;
    const int n0 = blockIdx.x * 32, k0 = blockIdx.y * 32;
    const int x = threadIdx.x & 31, y = threadIdx.x >> 5;
#pragma unroll
    for (int j = 0; j < 32; j += 8)
        t[y + j][x] = s[(size_t)(k0 + y + j) * N + n0 + x];
    __syncthreads();
#pragma unroll
    for (int j = 0; j < 32; j += 8)
        d[(size_t)(n0 + y + j) * K + k0 + x] = tf32f(t[x][y + j]);
}

// --------------------------------- grouped gather-GEMM (mma.sync, tf32) ----
// BM=128, BN=128, BK=32. 256 threads = 8 warps, warp grid 2m x 4n,
// warp tile 64x32 (mi=0..3 m16 blocks, ni=0..3 n8 blocks).
// cp.async double-buffered staging; conflict-free [row][36] smem layout.
// P1: h = relu(x @ W1 + b1) -> tf32 rounded.   P2: y = h @ W2 + b2.
#define ROWF 36                          // floats per smem row (pad 32->36)
#define A_FLOATS (128 * ROWF)            // 4608
#define STAGE_FLOATS (2 * A_FLOATS)      // 9216 (A then B)
#define STAGE_BYTES (STAGE_FLOATS * 4)   // 36864
#define GEMM_SMEM (1024 + 2 * STAGE_BYTES)   // 74752

template <bool P1>
__global__ void __launch_bounds__(256, 2) moe_gemm(
    const float* __restrict__ ball)
{
    constexpr int KD = P1 ? DD : HH;
    constexpr int NC = P1 ? HH : DD;
    constexpr int NCHUNK = KD / 32;

    const int e = blockIdx.z;
    const int cnt = g_cnt[e];
    const int mbase = blockIdx.y * 128;
    if (mbase >= cnt) return;
    const int nbase = blockIdx.x * 128;

    extern __shared__ float sm[];
    int* sSrc = (int*)sm;            // [128]
    int* sDst = (int*)sm + 128;      // [128]
    const int tid = threadIdx.x;

    if (tid < 128) {
        int m = mbase + tid;
        int mc = m < cnt ? m : cnt - 1;          // clamp (stores masked later)
        sSrc[tid] = P1 ? g_tok[e][mc] : g_slot[e][mc];
        sDst[tid] = g_slot[e][mc];
    }
    __syncthreads();

    // --- staging assignments: 2 threads per row, 4 x 16B each per chunk ---
    const float* Abase = P1 ? g_xt : g_h;
    const float* Wt = P1 ? g_W1t : g_W2t;
    const int r = tid >> 1, part = tid & 1;
    const float* agp = Abase + (size_t)sSrc[r] * KD + part * 16;
    const float* bgp = Wt + ((size_t)e * NC + nbase + r) * KD + part * 16;
    const uint32_t smu = smem_u32(sm);
    const uint32_t arow_off = 1024 + (uint32_t)r * (ROWF * 4) + part * 64;
    const uint32_t brow_off = arow_off + A_FLOATS * 4;

    // issue one chunk's cp.asyncs into stage s
    auto issue = [&](int c, int s) {
        const uint32_t sb = (uint32_t)s * STAGE_BYTES;
        const float* ag = agp + c * 32;
        const float* bg = bgp + c * 32;
#pragma unroll
        for (int i = 0; i < 4; i++) cpa16(smu + sb + arow_off + i * 16, ag + i * 4);
#pragma unroll
        for (int i = 0; i < 4; i++) cpa16(smu + sb + brow_off + i * 16, bg + i * 4);
        CP_COMMIT();
    };

    const int warp = tid >> 5, lane = tid & 31;
    const int wm = (warp & 1) * 64;      // warp row base   (2 m-warps)
    const int wn = (warp >> 1) * 32;     // warp col base   (4 n-warps)
    const int grp = lane >> 2, q = lane & 3;

    float acc[4][4][4];
#pragma unroll
    for (int a = 0; a < 4; a++)
#pragma unroll
        for (int b = 0; b < 4; b++)
#pragma unroll
            for (int c = 0; c < 4; c++) acc[a][b][c] = 0.f;

    issue(0, 0);
    issue(1, 1);

    for (int c = 0; c < NCHUNK; c++) {
        const int s = c & 1;
        if (c + 1 < NCHUNK) CP_WAIT1(); else CP_WAIT0();
        __syncthreads();

        const float* As = sm + 256 + s * STAGE_FLOATS;     // [128][36]
        const float* Bs = As + A_FLOATS;                   // [128][36]

#pragma unroll
        for (int kk = 0; kk < 32; kk += 8) {
            float a[4][4], b[4][2];
#pragma unroll
            for (int mi = 0; mi < 4; mi++) {
                int row = (wm + mi * 16 + grp) * ROWF;
                a[mi][0] = As[row + kk + q];
                a[mi][1] = As[row + 8 * ROWF + kk + q];
                a[mi][2] = As[row + kk + q + 4];
                a[mi][3] = As[row + 8 * ROWF + kk + q + 4];
            }
#pragma unroll
            for (int ni = 0; ni < 4; ni++) {
                int col = (wn + ni * 8 + grp) * ROWF;
                b[ni][0] = Bs[col + kk + q];
                b[ni][1] = Bs[col + kk + q + 4];
            }
#pragma unroll
            for (int mi = 0; mi < 4; mi++)
#pragma unroll
                for (int ni = 0; ni < 4; ni++) {
                    asm volatile(
                        "mma.sync.aligned.m16n8k8.row.col.f32.tf32.tf32.f32 "
                        "{%0,%1,%2,%3}, {%4,%5,%6,%7}, {%8,%9}, {%0,%1,%2,%3};"
                        : "+f"(acc[mi][ni][0]), "+f"(acc[mi][ni][1]),
                          "+f"(acc[mi][ni][2]), "+f"(acc[mi][ni][3])
                        : "r"(__float_as_uint(a[mi][0])), "r"(__float_as_uint(a[mi][1])),
                          "r"(__float_as_uint(a[mi][2])), "r"(__float_as_uint(a[mi][3])),
                          "r"(__float_as_uint(b[ni][0])), "r"(__float_as_uint(b[ni][1])));
                }
        }
        __syncthreads();
        if (c + 2 < NCHUNK) issue(c + 2, s);
    }

    // ------------------------------------------------------- epilogue ----
    const float* bias = ball + (size_t)e * NC + nbase;
    float* Out = P1 ? g_h : g_y;
#pragma unroll
    for (int ni = 0; ni < 4; ni++) {
        int col = wn + ni * 8 + q * 2;
        float bv0 = bias[col], bv1 = bias[col + 1];
#pragma unroll
        for (int mi = 0; mi < 4; mi++) {
#pragma unroll
            for (int h = 0; h < 2; h++) {
                int rl = wm + mi * 16 + grp + h * 8;
                if (mbase + rl < cnt) {
                    float v0 = acc[mi][ni][2 * h]     + bv0;
                    float v1 = acc[mi][ni][2 * h + 1] + bv1;
                    if (P1) {
                        v0 = tf32f(fmaxf(v0, 0.f));   // pre-round for GEMM2
                        v1 = tf32f(fmaxf(v1, 0.f));
                    }
                    float* op = Out + (size_t)sDst[rl] * NC + nbase + col;
                    *(float2*)op = make_float2(v0, v1);
                }
            }
        }
    }
}

// ------------------------------------------------------------- combine ----
__global__ void __launch_bounds__(256) moe_combine(float* __restrict__ out) {
    int i = blockIdx.x * 256 + threadIdx.x;
    int t = i >> 8;
    int d4 = i & 255;
    float gv0 = g_gate[2 * t], gv1 = g_gate[2 * t + 1];
    const float4* y4 = (const float4*)g_y;
    float4 a = y4[(size_t)(2 * t) * 256 + d4];
    float4 b = y4[(size_t)(2 * t) * 256 + 256 + d4];
    float4 r;
    r.x = gv0 * a.x + gv1 * b.x;
    r.y = gv0 * a.y + gv1 * b.y;
    r.z = gv0 * a.z + gv1 * b.z;
    r.w = gv0 * a.w + gv1 * b.w;
    ((float4*)out)[i] = r;
}

// ---------------------------------------------------------------- launch --
extern "C" void kernel_launch(void* const* d_in, const int* in_sizes, int n_in,
                              void* d_out, int out_size) {
    const float* x  = (const float*)d_in[0];
    const float* Wg = (const float*)d_in[1];
    const float* bg = (const float*)d_in[2];
    const float* W1 = (const float*)d_in[3];
    const float* b1 = (const float*)d_in[4];
    const float* W2 = (const float*)d_in[5];
    const float* b2 = (const float*)d_in[6];
    float* out = (float*)d_out;

    cudaFuncSetAttribute(moe_gemm<true>,
                         cudaFuncAttributeMaxDynamicSharedMemorySize, GEMM_SMEM);
    cudaFuncSetAttribute(moe_gemm<false>,
                         cudaFuncAttributeMaxDynamicSharedMemorySize, GEMM_SMEM);

    moe_init<<<1, 32>>>();
    moe_gate<<<TT / 8, 256>>>(x, Wg, bg);
    x_cvt<<<(TT * DD / 4) / 256, 256>>>((const float4*)x);
    transpose_cvt<true ><<<dim3(HH / 32, DD / 32, EE), 256>>>(W1);
    transpose_cvt<false><<<dim3(DD / 32, HH / 32, EE), 256>>>(W2);
    {   // GEMM1: N tiles of 128 over HH, worst-case M tiles of 128, E experts
        dim3 g(HH / 128, TT / 128, EE);
        moe_gemm<true><<<g, 256, GEMM_SMEM>>>(b1);
    }
    {   // GEMM2
        dim3 g(DD / 128, TT / 128, EE);
        moe_gemm<false><<<g, 256, GEMM_SMEM>>>(b2);
    }
    moe_combine<<<(TT * DD / 4) / 256, 256>>>(out);
}

// round 14
// speedup vs baseline: 1.6302x; 1.0890x over previous
#include <cuda_runtime.h>
#include <math.h>
#include <cstdint>

// Problem constants (B=4, N=4096, D=1024, E=8, K=2)
#define TT 16384              // tokens = B*N
#define DD 1024               // model dim
#define HH 2048               // hidden = 2*D
#define EE 8                  // experts
#define SLOTS (2 * TT)        // token-expert assignment slots (K=2)

// ---------------- scratch (no allocations allowed -> __device__ globals) ---
__device__ int   g_cnt[EE];
__device__ int   g_tok [EE][TT];
__device__ int   g_slot[EE][TT];
__device__ float g_gate[SLOTS];
__device__ float g_xt[(size_t)TT * DD];            // tf32-rounded x (64 MB)
__device__ float g_h[(size_t)SLOTS * HH];          // tf32-rounded hidden (256 MB)
__device__ float g_y[(size_t)SLOTS * DD];          // fp32 expert outputs (128 MB)
__device__ float g_W1t[(size_t)EE * HH * DD];      // W1^T [E][N=HH][K=DD], tf32
__device__ float g_W2t[(size_t)EE * DD * HH];      // W2^T [E][N=DD][K=HH], tf32

// ------------------------------------------------------------- helpers ----
__device__ __forceinline__ float tf32f(float x) {
    unsigned r;
    asm("cvt.rna.tf32.f32 %0, %1;" : "=r"(r) : "f"(x));
    return __uint_as_float(r);
}
__device__ __forceinline__ uint32_t smem_u32(const void* p) {
    uint32_t a;
    asm("{ .reg .u64 t; cvta.to.shared.u64 t, %1; cvt.u32.u64 %0, t; }"
        : "=r"(a) : "l"(p));
    return a;
}
__device__ __forceinline__ void cpa16(uint32_t saddr, const float* g) {
    asm volatile("cp.async.cg.shared.global [%0], [%1], 16;"
                 :: "r"(saddr), "l"(g) : "memory");
}
#define CP_COMMIT() asm volatile("cp.async.commit_group;" ::: "memory")
#define CP_WAIT1()  asm volatile("cp.async.wait_group 1;" ::: "memory")
#define CP_WAIT0()  asm volatile("cp.async.wait_group 0;" ::: "memory")

// ---------------------------------------------------------------- init ----
__global__ void moe_init() {
    if (threadIdx.x < EE) g_cnt[threadIdx.x] = 0;
}

// ----------------------------------------------------- x -> tf32 round ----
__global__ void __launch_bounds__(256) x_cvt(const float4* __restrict__ x) {
    int i = blockIdx.x * 256 + threadIdx.x;   // TT*DD/4 elements
    float4 v = x[i];
    v.x = tf32f(v.x); v.y = tf32f(v.y); v.z = tf32f(v.z); v.w = tf32f(v.w);
    ((float4*)g_xt)[i] = v;
}

// -------------------------------------------------------------- gating ----
__global__ void __launch_bounds__(256) moe_gate(
    const float* __restrict__ x, const float* __restrict__ Wg,
    const float* __restrict__ bg)
{
    __shared__ float sWgT[EE][DD];
    const int tid = threadIdx.x;
    for (int i = tid; i < EE * DD; i += 256) {
        int e = i >> 10, d = i & (DD - 1);
        sWgT[e][d] = Wg[d * EE + e];
    }
    __syncthreads();

    const int warp = tid >> 5, lane = tid & 31;
    const int t = blockIdx.x * 8 + warp;

    float acc[EE];
#pragma unroll
    for (int e = 0; e < EE; e++) acc[e] = 0.f;

    const float* xr = x + (size_t)t * DD;
    for (int d = lane; d < DD; d += 32) {
        float xv = xr[d];
#pragma unroll
        for (int e = 0; e < EE; e++) acc[e] += xv * sWgT[e][d];
    }
#pragma unroll
    for (int e = 0; e < EE; e++) {
#pragma unroll
        for (int off = 16; off > 0; off >>= 1)
            acc[e] += __shfl_xor_sync(0xffffffffu, acc[e], off);
    }

    if (lane == 0) {
        float l[EE];
#pragma unroll
        for (int e = 0; e < EE; e++) l[e] = acc[e] + bg[e];
        int i0 = 0; float m0 = l[0];
#pragma unroll
        for (int e = 1; e < EE; e++) if (l[e] > m0) { m0 = l[e]; i0 = e; }
        int i1 = -1; float m1 = -1e30f;
#pragma unroll
        for (int e = 0; e < EE; e++)
            if (e != i0 && l[e] > m1) { m1 = l[e]; i1 = e; }
        float e1 = expf(m1 - m0);
        float inv = 1.0f / (1.0f + e1);

        int p0 = atomicAdd(&g_cnt[i0], 1);
        g_tok[i0][p0] = t;  g_slot[i0][p0] = 2 * t;
        int p1 = atomicAdd(&g_cnt[i1], 1);
        g_tok[i1][p1] = t;  g_slot[i1][p1] = 2 * t + 1;
        g_gate[2 * t]     = inv;
        g_gate[2 * t + 1] = e1 * inv;
    }
}

// --------------------------------------- weight transpose + tf32 convert --
// W [E][K][N] (N contiguous) -> Wt [E][N][K] (K contiguous), tf32-rounded.
template <bool ONE>
__global__ void __launch_bounds__(256) transpose_cvt(const float* __restrict__ src) {
    constexpr int K = ONE ? DD : HH;
    constexpr int N = ONE ? HH : DD;
    float* dst = ONE ? g_W1t : g_W2t;
    __shared__ float t[32][33];
    const size_t esz = (size_t)K * N;
    const float* s = src + blockIdx.z * esz;
    float* d = dst + blockIdx.z * esz;
    const int n0 = blockIdx.x * 32, k0 = blockIdx.y * 32;
    const int x = threadIdx.x & 31, y = threadIdx.x >> 5;
#pragma unroll
    for (int j = 0; j < 32; j += 8)
        t[y + j][x] = s[(size_t)(k0 + y + j) * N + n0 + x];
    __syncthreads();
#pragma unroll
    for (int j = 0; j < 32; j += 8)
        d[(size_t)(n0 + y + j) * K + k0 + x] = tf32f(t[x][y + j]);
}

// --------------------------------- grouped gather-GEMM (mma.sync, tf32) ----
// BM=256, BN=128, BK=32. 256 threads = 8 warps, warp grid 4m x 2n,
// warp tile 64x64 (mi 0..3 m16 blocks, ni 0..7 n8 blocks) -> 1.0 LDS/mma.
// 1 CTA/SM. cp.async double-buffered; conflict-free [row][36] layout.
// P1: h = relu(x @ W1 + b1) -> tf32 rounded.   P2: y = h @ W2 + b2.
#define ROWF 36                          // floats per smem row (pad 32->36)
#define A_ROWS 256
#define B_ROWS 128
#define A_FLOATS (A_ROWS * ROWF)         // 9216
#define B_FLOATS (B_ROWS * ROWF)         // 4608
#define STAGE_FLOATS (A_FLOATS + B_FLOATS)   // 13824
#define STAGE_BYTES (STAGE_FLOATS * 4)       // 55296
#define GEMM_SMEM (2048 + 2 * STAGE_BYTES)   // 112640

template <bool P1>
__global__ void __launch_bounds__(256, 1) moe_gemm(
    const float* __restrict__ ball)
{
    constexpr int KD = P1 ? DD : HH;
    constexpr int NC = P1 ? HH : DD;
    constexpr int NCHUNK = KD / 32;

    const int e = blockIdx.z;
    const int cnt = g_cnt[e];
    const int mbase = blockIdx.y * 256;
    if (mbase >= cnt) return;
    const int nbase = blockIdx.x * 128;

    extern __shared__ float sm[];
    int* sSrc = (int*)sm;            // [256]
    int* sDst = (int*)sm + 256;      // [256]  (data starts at float 512)
    const int tid = threadIdx.x;

    {
        int m = mbase + tid;
        int mc = m < cnt ? m : cnt - 1;          // clamp (stores masked later)
        sSrc[tid] = P1 ? g_tok[e][mc] : g_slot[e][mc];
        sDst[tid] = g_slot[e][mc];
    }
    __syncthreads();

    // --- staging: 768 tasks of 64B (A: 512, B: 256) = 3 tasks/thread ------
    const float* Abase = P1 ? g_xt : g_h;
    const float* Wt = P1 ? g_W1t : g_W2t;
    const uint32_t smu = smem_u32(sm);
    const float* gp[3];
    uint32_t so[3];
#pragma unroll
    for (int i = 0; i < 3; i++) {
        int t = tid + 256 * i;
        if (t < 512) {
            int row = t >> 1, half = t & 1;
            gp[i] = Abase + (size_t)sSrc[row] * KD + half * 16;
            so[i] = 2048 + (uint32_t)(row * ROWF + half * 16) * 4;
        } else {
            int idx = t - 512;
            int row = idx >> 1, half = idx & 1;
            gp[i] = Wt + ((size_t)e * NC + nbase + row) * KD + half * 16;
            so[i] = 2048 + (uint32_t)(A_FLOATS + row * ROWF + half * 16) * 4;
        }
    }

    auto issue = [&](int c, int s) {
        const uint32_t sb = smu + (uint32_t)s * STAGE_BYTES;
#pragma unroll
        for (int i = 0; i < 3; i++) {
            const float* g = gp[i] + c * 32;
#pragma unroll
            for (int j = 0; j < 4; j++) cpa16(sb + so[i] + j * 16, g + j * 4);
        }
        CP_COMMIT();
    };

    const int warp = tid >> 5, lane = tid & 31;
    const int wm = (warp & 3) * 64;      // warp row base   (4 m-warps)
    const int wn = (warp >> 2) * 64;     // warp col base   (2 n-warps)
    const int grp = lane >> 2, q = lane & 3;

    float acc[4][8][4];
#pragma unroll
    for (int a = 0; a < 4; a++)
#pragma unroll
        for (int b = 0; b < 8; b++)
#pragma unroll
            for (int c = 0; c < 4; c++) acc[a][b][c] = 0.f;

    issue(0, 0);
    issue(1, 1);

    for (int c = 0; c < NCHUNK; c++) {
        const int s = c & 1;
        if (c + 1 < NCHUNK) CP_WAIT1(); else CP_WAIT0();
        __syncthreads();

        const float* As = sm + 512 + s * STAGE_FLOATS;     // [256][36]
        const float* Bs = As + A_FLOATS;                   // [128][36]

#pragma unroll
        for (int kk = 0; kk < 32; kk += 8) {
            float a[4][4], b[8][2];
#pragma unroll
            for (int mi = 0; mi < 4; mi++) {
                int row = (wm + mi * 16 + grp) * ROWF;
                a[mi][0] = As[row + kk + q];
                a[mi][1] = As[row + 8 * ROWF + kk + q];
                a[mi][2] = As[row + kk + q + 4];
                a[mi][3] = As[row + 8 * ROWF + kk + q + 4];
            }
#pragma unroll
            for (int ni = 0; ni < 8; ni++) {
                int col = (wn + ni * 8 + grp) * ROWF;
                b[ni][0] = Bs[col + kk + q];
                b[ni][1] = Bs[col + kk + q + 4];
            }
#pragma unroll
            for (int mi = 0; mi < 4; mi++)
#pragma unroll
                for (int ni = 0; ni < 8; ni++) {
                    asm volatile(
                        "mma.sync.aligned.m16n8k8.row.col.f32.tf32.tf32.f32 "
                        "{%0,%1,%2,%3}, {%4,%5,%6,%7}, {%8,%9}, {%0,%1,%2,%3};"
                        : "+f"(acc[mi][ni][0]), "+f"(acc[mi][ni][1]),
                          "+f"(acc[mi][ni][2]), "+f"(acc[mi][ni][3])
                        : "r"(__float_as_uint(a[mi][0])), "r"(__float_as_uint(a[mi][1])),
                          "r"(__float_as_uint(a[mi][2])), "r"(__float_as_uint(a[mi][3])),
                          "r"(__float_as_uint(b[ni][0])), "r"(__float_as_uint(b[ni][1])));
                }
        }
        __syncthreads();
        if (c + 2 < NCHUNK) issue(c + 2, s);
    }

    // ------------------------------------------------------- epilogue ----
    const float* bias = ball + (size_t)e * NC + nbase;
    float* Out = P1 ? g_h : g_y;
#pragma unroll
    for (int ni = 0; ni < 8; ni++) {
        int col = wn + ni * 8 + q * 2;
        float bv0 = bias[col], bv1 = bias[col + 1];
#pragma unroll
        for (int mi = 0; mi < 4; mi++) {
#pragma unroll
            for (int h = 0; h < 2; h++) {
                int rl = wm + mi * 16 + grp + h * 8;
                if (mbase + rl < cnt) {
                    float v0 = acc[mi][ni][2 * h]     + bv0;
                    float v1 = acc[mi][ni][2 * h + 1] + bv1;
                    if (P1) {
                        v0 = tf32f(fmaxf(v0, 0.f));   // pre-round for GEMM2
                        v1 = tf32f(fmaxf(v1, 0.f));
                    }
                    float* op = Out + (size_t)sDst[rl] * NC + nbase + col;
                    *(float2*)op = make_float2(v0, v1);
                }
            }
        }
    }
}

// ------------------------------------------------------------- combine ----
__global__ void __launch_bounds__(256) moe_combine(float* __restrict__ out) {
    int i = blockIdx.x * 256 + threadIdx.x;
    int t = i >> 8;
    int d4 = i & 255;
    float gv0 = g_gate[2 * t], gv1 = g_gate[2 * t + 1];
    const float4* y4 = (const float4*)g_y;
    float4 a = y4[(size_t)(2 * t) * 256 + d4];
    float4 b = y4[(size_t)(2 * t) * 256 + 256 + d4];
    float4 r;
    r.x = gv0 * a.x + gv1 * b.x;
    r.y = gv0 * a.y + gv1 * b.y;
    r.z = gv0 * a.z + gv1 * b.z;
    r.w = gv0 * a.w + gv1 * b.w;
    ((float4*)out)[i] = r;
}

// ---------------------------------------------------------------- launch --
extern "C" void kernel_launch(void* const* d_in, const int* in_sizes, int n_in,
                              void* d_out, int out_size) {
    const float* x  = (const float*)d_in[0];
    const float* Wg = (const float*)d_in[1];
    const float* bg = (const float*)d_in[2];
    const float* W1 = (const float*)d_in[3];
    const float* b1 = (const float*)d_in[4];
    const float* W2 = (const float*)d_in[5];
    const float* b2 = (const float*)d_in[6];
    float* out = (float*)d_out;

    cudaFuncSetAttribute(moe_gemm<true>,
                         cudaFuncAttributeMaxDynamicSharedMemorySize, GEMM_SMEM);
    cudaFuncSetAttribute(moe_gemm<false>,
                         cudaFuncAttributeMaxDynamicSharedMemorySize, GEMM_SMEM);

    moe_init<<<1, 32>>>();
    moe_gate<<<TT / 8, 256>>>(x, Wg, bg);
    x_cvt<<<(TT * DD / 4) / 256, 256>>>((const float4*)x);
    transpose_cvt<true ><<<dim3(HH / 32, DD / 32, EE), 256>>>(W1);
    transpose_cvt<false><<<dim3(DD / 32, HH / 32, EE), 256>>>(W2);
    {   // GEMM1: N tiles of 128 over HH, worst-case M tiles of 256, E experts
        dim3 g(HH / 128, TT / 256, EE);
        moe_gemm<true><<<g, 256, GEMM_SMEM>>>(b1);
    }
    {   // GEMM2
        dim3 g(DD / 128, TT / 256, EE);
        moe_gemm<false><<<g, 256, GEMM_SMEM>>>(b2);
    }
    moe_combine<<<(TT * DD / 4) / 256, 256>>>(out);
}